// round 12
// baseline (speedup 1.0000x reference)
#include <cuda_runtime.h>
#include <cuda_bf16.h>
#include <cstdint>

// Problem constants
#define MTOK 32768            // B*T = 16*2048
#define DDIM 256
#define KCB  1024
#define QST  4
#define QUANT_ELEMS (MTOK*DDIM)            // 8388608
#define CB_ELEMS    (QST*KCB*DDIM)         // 1048576
#define IDX_OFF     QUANT_ELEMS
#define LOSS_OFF    (QUANT_ELEMS + QST*MTOK)

// Tiling
#define BM 128                 // tokens per CTA
#define BN 64                  // codes per chunk (16 chunks)
#define NTHREADS 512           // 16 warps -> 4/SMSP

// Packed fp32x2 FMA (Blackwell): acc += a * b, lanewise on 2xfp32
#define FMA2(acc, a, b) \
    asm("fma.rn.f32x2 %0, %1, %2, %0;" : "+l"(acc) : "l"(a), "l"(b))
#define DUP2(dst, s) \
    asm("mov.b64 %0, {%1, %1};" : "=l"(dst) : "r"(s))

__device__ __forceinline__ float lo32(uint64_t v) {
    return __uint_as_float((uint32_t)v);
}
__device__ __forceinline__ float hi32(uint64_t v) {
    return __uint_as_float((uint32_t)(v >> 32));
}

// ---------------- device scratch (no allocations allowed) ----------------
__device__ float  g_cnorm[QST*KCB];   // ||c_k||^2 per stage
__device__ double g_loss;             // sum over stages of ||new residual||^2

// ---------------- prep: zero loss accumulator + codebook norms ----------------
__global__ void prep_kernel(const float* __restrict__ cb) {
    if (blockIdx.x == 0 && threadIdx.x == 0) g_loss = 0.0;
    int warp  = blockIdx.x * (blockDim.x >> 5) + (threadIdx.x >> 5);
    int lane  = threadIdx.x & 31;
    int nwarp = gridDim.x * (blockDim.x >> 5);
    for (int row = warp; row < QST*KCB; row += nwarp) {
        const float* p = cb + (size_t)row * DDIM;
        float s = 0.f;
        #pragma unroll
        for (int j = 0; j < DDIM/32; j++) {
            float v = p[j*32 + lane];
            s = fmaf(v, v, s);
        }
        #pragma unroll
        for (int o = 16; o; o >>= 1) s += __shfl_xor_sync(0xffffffffu, s, o);
        if (lane == 0) g_cnorm[row] = s;
    }
}

// ---------------- fused persistent RVQ kernel: all 4 stages, one launch --------
// Residual tile lives in smem As (transposed [d][tok]) the whole time.
// Score matches the reference op sequence: fl(fl(rnorm - fl(2*dot)) + cnorm).
extern "C" __global__ void __launch_bounds__(NTHREADS, 1)
rvq_kernel(const float* __restrict__ x, const float* __restrict__ cb,
           float* __restrict__ out) {
    extern __shared__ float smem[];
    float* As = smem;                 // [DDIM][BM]  128 KB
    float* Cs = smem + DDIM*BM;       // [DDIM][BN]   64 KB (reused as scratch)
    __shared__ int   s_idx[BM];
    __shared__ float s_rnorm[BM];
    __shared__ float s_wsum[NTHREADS/32];

    const int tid     = threadIdx.x;
    const int tokbase = blockIdx.x * BM;

    // Update/rnorm mapping: consecutive lanes -> consecutive tokens (conflict-free)
    const int utok = tid & (BM-1);
    const int ug   = tid >> 7;        // 0..3, 64 dims each

    // ---- load x tile transposed into As (residual starts = x) ----
    {
        #pragma unroll
        for (int d4 = ug; d4 < DDIM/4; d4 += (NTHREADS/BM)) {
            float4 v = *(const float4*)(x + (size_t)(tokbase + utok) * DDIM + d4*4);
            As[(d4*4+0)*BM + utok] = v.x;
            As[(d4*4+1)*BM + utok] = v.y;
            As[(d4*4+2)*BM + utok] = v.z;
            As[(d4*4+3)*BM + utok] = v.w;
        }
    }
    __syncthreads();

    // ---- initial per-token rnorm = ||x_token||^2 ----
    {
        float partial = 0.f;
        #pragma unroll
        for (int j = 0; j < 64; j++) {
            float v = As[(ug*64 + j)*BM + utok];
            partial = fmaf(v, v, partial);
        }
        float* s_part = Cs;   // [4][BM]
        s_part[ug*BM + utok] = partial;
        __syncthreads();
        if (tid < BM) {
            s_rnorm[tid] = ((s_part[0*BM + tid] + s_part[1*BM + tid])
                          + (s_part[2*BM + tid] + s_part[3*BM + tid]));
        }
        // (visible after the stage-start __syncthreads below)
    }

    // Codebook loader mapping: each thread owns 128B contiguous of one code row.
    // 512 threads = 64 codes x 8 dim-groups (32 dims each).
    const int lcode = tid & (BN-1);
    const int ldg   = tid >> 6;        // 0..7

    const int tx = tid & 63;   // token pair: tokens tx*2, tx*2+1
    const int ty = tid >> 6;   // code group: codes ty*8..ty*8+7 within chunk (0..7)

    for (int q = 0; q < QST; q++) {
        const float* cbq    = cb + (size_t)q * KCB * DDIM;
        const float* cnormq = g_cnorm + q * KCB;
        const float* lsrc   = cbq + (size_t)lcode * DDIM + ldg * 32;

        // Prefetch chunk 0 (8 x float4 = 128B per thread) + its cnorms
        float4 pf[8];
        #pragma unroll
        for (int i = 0; i < 8; i++) pf[i] = *(const float4*)(lsrc + i*4);
        float4 cn0 = __ldg((const float4*)(cnormq + ty*8));
        float4 cn1 = __ldg((const float4*)(cnormq + ty*8 + 4));

        float bestv[2] = {3.4e38f, 3.4e38f};
        int   besti[2] = {0, 0};

        __syncthreads();   // As + s_rnorm ready

        const float rn0 = s_rnorm[tx*2 + 0];
        const float rn1 = s_rnorm[tx*2 + 1];

        for (int nc = 0; nc < KCB/BN; nc++) {
            // Store prefetched chunk nc into Cs[d][code] (consecutive lcode -> conflict-free)
            {
                float* dst = Cs + (ldg*32)*BN + lcode;
                #pragma unroll
                for (int i = 0; i < 8; i++) {
                    dst[(i*4+0)*BN] = pf[i].x;
                    dst[(i*4+1)*BN] = pf[i].y;
                    dst[(i*4+2)*BN] = pf[i].z;
                    dst[(i*4+3)*BN] = pf[i].w;
                }
            }
            __syncthreads();

            // Prefetch next chunk (+ its cnorms) while computing this one
            float4 cnA = cn0, cnB = cn1;
            if (nc + 1 < KCB/BN) {
                const float* nsrc = lsrc + (size_t)(nc+1) * BN * DDIM;
                #pragma unroll
                for (int i = 0; i < 8; i++) pf[i] = *(const float4*)(nsrc + i*4);
                cn0 = __ldg((const float4*)(cnormq + (nc+1)*BN + ty*8));
                cn1 = __ldg((const float4*)(cnormq + (nc+1)*BN + ty*8 + 4));
            }

            // Packed f32x2 GEMM micro-tile: 2 tokens x 8 codes (4 code-pairs).
            // Split L/H accumulation (two 128-term chains) for low dot noise.
            uint64_t accL[2][4] = {{0ull,0ull,0ull,0ull},{0ull,0ull,0ull,0ull}};
            uint64_t accH[2][4] = {{0ull,0ull,0ull,0ull},{0ull,0ull,0ull,0ull}};

            const float* ap = As + tx*2;
            const float* cp = Cs + ty*8;
            #pragma unroll 8
            for (int d = 0; d < DDIM/2; d++) {
                float2 a = *(const float2*)(ap + d*BM);
                ulonglong2 c01 = *(const ulonglong2*)(cp + d*BN);
                ulonglong2 c23 = *(const ulonglong2*)(cp + d*BN + 4);
                uint64_t a0d, a1d;
                DUP2(a0d, __float_as_uint(a.x));
                DUP2(a1d, __float_as_uint(a.y));
                FMA2(accL[0][0], a0d, c01.x);
                FMA2(accL[0][1], a0d, c01.y);
                FMA2(accL[0][2], a0d, c23.x);
                FMA2(accL[0][3], a0d, c23.y);
                FMA2(accL[1][0], a1d, c01.x);
                FMA2(accL[1][1], a1d, c01.y);
                FMA2(accL[1][2], a1d, c23.x);
                FMA2(accL[1][3], a1d, c23.y);
            }
            #pragma unroll 8
            for (int d = DDIM/2; d < DDIM; d++) {
                float2 a = *(const float2*)(ap + d*BM);
                ulonglong2 c01 = *(const ulonglong2*)(cp + d*BN);
                ulonglong2 c23 = *(const ulonglong2*)(cp + d*BN + 4);
                uint64_t a0d, a1d;
                DUP2(a0d, __float_as_uint(a.x));
                DUP2(a1d, __float_as_uint(a.y));
                FMA2(accH[0][0], a0d, c01.x);
                FMA2(accH[0][1], a0d, c01.y);
                FMA2(accH[0][2], a0d, c23.x);
                FMA2(accH[0][3], a0d, c23.y);
                FMA2(accH[1][0], a1d, c01.x);
                FMA2(accH[1][1], a1d, c01.y);
                FMA2(accH[1][2], a1d, c23.x);
                FMA2(accH[1][3], a1d, c23.y);
            }

            // score = (rnorm - 2*dot) + cnorm, reference op order, no contraction.
            // Codes ascending (pair p, half h) + strict < => first-index ties.
            const float cna[8] = {cnA.x, cnA.y, cnA.z, cnA.w,
                                  cnB.x, cnB.y, cnB.z, cnB.w};
            #pragma unroll
            for (int p = 0; p < 4; p++) {
                #pragma unroll
                for (int h = 0; h < 2; h++) {
                    int code = nc*BN + ty*8 + p*2 + h;
                    float cn = cna[p*2 + h];
                    {
                        float dl = h ? hi32(accL[0][p]) : lo32(accL[0][p]);
                        float dh = h ? hi32(accH[0][p]) : lo32(accH[0][p]);
                        float dot = __fadd_rn(dl, dh);
                        float s = __fadd_rn(__fsub_rn(rn0, __fmul_rn(2.0f, dot)), cn);
                        if (s < bestv[0]) { bestv[0] = s; besti[0] = code; }
                    }
                    {
                        float dl = h ? hi32(accL[1][p]) : lo32(accL[1][p]);
                        float dh = h ? hi32(accH[1][p]) : lo32(accH[1][p]);
                        float dot = __fadd_rn(dl, dh);
                        float s = __fadd_rn(__fsub_rn(rn1, __fmul_rn(2.0f, dot)), cn);
                        if (s < bestv[1]) { bestv[1] = s; besti[1] = code; }
                    }
                }
            }
            __syncthreads();   // done reading Cs before it is overwritten
        }

        // ---- cross-thread (ty) argmin reduction, reusing Cs: rv[8][BM], ri[8][BM]
        float* rv = Cs;
        int*   ri = (int*)(Cs + 8*BM);
        #pragma unroll
        for (int i = 0; i < 2; i++) {
            rv[ty*BM + tx*2 + i] = bestv[i];
            ri[ty*BM + tx*2 + i] = besti[i];
        }
        __syncthreads();
        if (tid < BM) {
            float bv = rv[tid];
            int   bi = ri[tid];
            #pragma unroll
            for (int t = 1; t < 8; t++) {
                float v  = rv[t*BM + tid];
                int   ix = ri[t*BM + tid];
                if (v < bv || (v == bv && ix < bi)) { bv = v; bi = ix; }
            }
            s_idx[tid] = bi;
            out[IDX_OFF + q*MTOK + tokbase + tid] = (float)bi;
        }
        __syncthreads();

        // ---- update: residual -= codeword (in smem, conflict-free), partials ----
        {
            const int idx = s_idx[utok];
            const float4* crow = (const float4*)(cbq + (size_t)idx * DDIM) + ug*16;
            float partial = 0.f;
            #pragma unroll
            for (int j = 0; j < 16; j++) {
                float4 c = crow[j];
                int d = ug*64 + j*4;
                float v0 = As[(d+0)*BM + utok] - c.x;
                float v1 = As[(d+1)*BM + utok] - c.y;
                float v2 = As[(d+2)*BM + utok] - c.z;
                float v3 = As[(d+3)*BM + utok] - c.w;
                As[(d+0)*BM + utok] = v0;
                As[(d+1)*BM + utok] = v1;
                As[(d+2)*BM + utok] = v2;
                As[(d+3)*BM + utok] = v3;
                partial = fmaf(v0, v0, partial);
                partial = fmaf(v1, v1, partial);
                partial = fmaf(v2, v2, partial);
                partial = fmaf(v3, v3, partial);
            }
            float* s_part = Cs;   // [4][BM], safe: Cs not otherwise in use now
            s_part[ug*BM + utok] = partial;
            __syncthreads();

            // per-token new rnorm (for next stage) + block loss sum
            float myr = 0.f;
            if (tid < BM) {
                myr = ((s_part[0*BM + tid] + s_part[1*BM + tid])
                     + (s_part[2*BM + tid] + s_part[3*BM + tid]));
                s_rnorm[tid] = myr;
            }
            #pragma unroll
            for (int o = 16; o; o >>= 1)
                myr += __shfl_xor_sync(0xffffffffu, myr, o);
            if (tid < BM && (tid & 31) == 0) s_wsum[tid >> 5] = myr;
            __syncthreads();
            if (tid == 0) {
                float tot = ((s_wsum[0] + s_wsum[1]) + (s_wsum[2] + s_wsum[3]));
                atomicAdd(&g_loss, (double)tot);
            }
        }
        __syncthreads();   // As + s_rnorm consistent before next stage / epilogue
    }

    // ---- epilogue: quant = x - residual_final ----
    {
        #pragma unroll
        for (int d4 = ug; d4 < DDIM/4; d4 += (NTHREADS/BM)) {
            float4 v = *(const float4*)(x + (size_t)(tokbase + utok) * DDIM + d4*4);
            v.x -= As[(d4*4+0)*BM + utok];
            v.y -= As[(d4*4+1)*BM + utok];
            v.z -= As[(d4*4+2)*BM + utok];
            v.w -= As[(d4*4+3)*BM + utok];
            *(float4*)(out + (size_t)(tokbase + utok) * DDIM + d4*4) = v;
        }
    }
}

// ---------------- loss epilogue: broadcast the 4 identical scalars ----------------
__global__ void loss_kernel(float* __restrict__ out) {
    if (threadIdx.x < QST) {
        float loss = (float)(1.25 * g_loss / (double)QUANT_ELEMS);
        out[LOSS_OFF + threadIdx.x] = loss;
    }
}

// ---------------- launch ----------------
extern "C" void kernel_launch(void* const* d_in, const int* in_sizes, int n_in,
                              void* d_out, int out_size) {
    // Resolve inputs by element count (robust to ordering): x has 8388608,
    // codebooks has 1048576.
    const float* x  = (const float*)d_in[0];
    const float* cb = (const float*)d_in[1];
    if (n_in >= 2 && in_sizes[0] == CB_ELEMS && in_sizes[1] == QUANT_ELEMS) {
        x  = (const float*)d_in[1];
        cb = (const float*)d_in[0];
    }
    float* out = (float*)d_out;

    const int smem_bytes = (DDIM*BM + DDIM*BN) * (int)sizeof(float);  // 192 KB
    cudaFuncSetAttribute((const void*)rvq_kernel,
                         cudaFuncAttributeMaxDynamicSharedMemorySize, smem_bytes);

    prep_kernel<<<148, 256>>>(cb);
    rvq_kernel<<<MTOK/BM, NTHREADS, smem_bytes>>>(x, cb, out);
    loss_kernel<<<1, 32>>>(out);
}